// round 3
// baseline (speedup 1.0000x reference)
#include <cuda_runtime.h>

#define BB 4
#define NSEC 1024
#define NPRIM 256
#define NNODES 1536
#define NH 4
#define OF 32
#define FG 128

// ---------------- scratch (static device memory, no allocs) ----------------
__device__ float g_scratch[4700000];

__device__ __forceinline__ float lrelu(float x) { return x > 0.f ? x : 0.2f * x; }
__device__ __forceinline__ float warpSum(float v) {
    #pragma unroll
    for (int o = 16; o > 0; o >>= 1) v += __shfl_xor_sync(0xffffffffu, v, o);
    return v;
}

// ---------------- GEMM: C[M,N] = A[M,K] @ B[K,N] (+bias)(+relu)(+sd) -------
// 64x128 tile, BK=16, 256 threads, 4x8 microtile. Optional fused per-(row,head)
// attention scalars s,d (for the xp GEMMs) and per-block partial sums (FC1).
__global__ void gemm_kernel(const float* __restrict__ A, const float* __restrict__ B,
                            const float* __restrict__ bias, float* __restrict__ C,
                            int M, int N, int K, int doRelu, float* __restrict__ part,
                            const float* __restrict__ a_s, const float* __restrict__ a_d,
                            float* __restrict__ s, float* __restrict__ d)
{
    __shared__ float As[16][64];
    __shared__ float Bs[16][128];
    int tid = threadIdx.x;
    int tx = tid & 15, ty = tid >> 4;
    int m0 = blockIdx.y * 64, n0 = blockIdx.x * 128;
    float acc[4][8] = {};
    int am = tid >> 2, ak = (tid & 3) << 2;
    int bk = tid >> 4, bn = (tid & 15) << 3;

    for (int k0 = 0; k0 < K; k0 += 16) {
        float4 a = *(const float4*)(A + (size_t)(m0 + am) * K + k0 + ak);
        As[ak + 0][am] = a.x; As[ak + 1][am] = a.y;
        As[ak + 2][am] = a.z; As[ak + 3][am] = a.w;
        *(float4*)&Bs[bk][bn]     = *(const float4*)(B + (size_t)(k0 + bk) * N + n0 + bn);
        *(float4*)&Bs[bk][bn + 4] = *(const float4*)(B + (size_t)(k0 + bk) * N + n0 + bn + 4);
        __syncthreads();
        #pragma unroll
        for (int k = 0; k < 16; k++) {
            float4 a4 = *(const float4*)&As[k][ty << 2];
            float4 bA = *(const float4*)&Bs[k][tx << 3];
            float4 bB = *(const float4*)&Bs[k][(tx << 3) + 4];
            float av[4] = {a4.x, a4.y, a4.z, a4.w};
            float bv[8] = {bA.x, bA.y, bA.z, bA.w, bB.x, bB.y, bB.z, bB.w};
            #pragma unroll
            for (int i = 0; i < 4; i++)
                #pragma unroll
                for (int j = 0; j < 8; j++)
                    acc[i][j] = fmaf(av[i], bv[j], acc[i][j]);
        }
        __syncthreads();
    }

    float bsum = 0.f;
    #pragma unroll
    for (int i = 0; i < 4; i++) {
        int row = m0 + (ty << 2) + i;
        #pragma unroll
        for (int j = 0; j < 8; j++) {
            int col = n0 + (tx << 3) + j;
            float v = acc[i][j];
            if (bias) v += bias[col];
            if (doRelu) v = fmaxf(v, 0.f);
            C[(size_t)row * N + col] = v;
            bsum += v;
        }
    }

    // Fused attention scalars: s,d per (row, head). Requires N==128, n0==0.
    if (s) {
        int h = tx >> 2;           // head 0..3 (cols tx*8..tx*8+7 lie in one head)
        int q = tx & 3;            // quarter of the head's 32 cols
        const float* asr = a_s + h * OF + q * 8;
        const float* adr = a_d + h * OF + q * 8;
        #pragma unroll
        for (int i = 0; i < 4; i++) {
            float ss = 0.f, dd = 0.f;
            #pragma unroll
            for (int j = 0; j < 8; j++) {
                ss = fmaf(acc[i][j], asr[j], ss);
                dd = fmaf(acc[i][j], adr[j], dd);
            }
            ss += __shfl_xor_sync(0xffffffffu, ss, 1);
            ss += __shfl_xor_sync(0xffffffffu, ss, 2);
            dd += __shfl_xor_sync(0xffffffffu, dd, 1);
            dd += __shfl_xor_sync(0xffffffffu, dd, 2);
            if (q == 0) {
                int row = m0 + (ty << 2) + i;
                int b = row / NNODES;
                int n = row - b * NNODES;
                s[(size_t)(b * NH + h) * NNODES + n] = ss;
                d[(size_t)(b * NH + h) * NNODES + n] = dd;
            }
        }
    }

    if (part) {
        __shared__ float red[256];
        red[tid] = bsum;
        __syncthreads();
        #pragma unroll
        for (int st = 128; st > 0; st >>= 1) {
            if (tid < st) red[tid] += red[tid + st];
            __syncthreads();
        }
        if (tid == 0) part[blockIdx.y * gridDim.x + blockIdx.x] = red[0];
    }
}

// ---------------- segment max of s over sec range & beam range -------------
__global__ void smax_kernel(const float* __restrict__ s, float* __restrict__ smax)
{
    __shared__ float red[256];
    int bh = blockIdx.x, tid = threadIdx.x;
    const float* sRow = s + (size_t)bh * NNODES;
    float m = fmaxf(fmaxf(sRow[tid], sRow[tid + 256]),
                    fmaxf(sRow[tid + 512], sRow[tid + 768]));
    red[tid] = m;
    __syncthreads();
    #pragma unroll
    for (int st = 128; st > 0; st >>= 1) {
        if (tid < st) red[tid] = fmaxf(red[tid], red[tid + st]);
        __syncthreads();
    }
    if (tid == 0) smax[bh * 2] = red[0];
    __syncthreads();
    red[tid] = sRow[NSEC + tid];
    __syncthreads();
    #pragma unroll
    for (int st = 128; st > 0; st >>= 1) {
        if (tid < st) red[tid] = fmaxf(red[tid], red[tid + st]);
        __syncthreads();
    }
    if (tid == 0) smax[bh * 2 + 1] = red[0];
}

// ---------------- sec-destination aggregation (GEMM-style, single pass) ----
// 64 dst x 32 feat tile, 128 threads, 4x4 microtile. 256 beam srcs + self.
__global__ void sec_agg2_kernel(const float* __restrict__ xp, const float* __restrict__ s,
                                const float* __restrict__ d, const float* __restrict__ smax,
                                const float* __restrict__ bias, float* __restrict__ out,
                                int outStrideB)
{
    __shared__ float xS[32 * 32];
    __shared__ float wS[64 * 33];
    __shared__ float sS[32];
    __shared__ float dS[64], mS[64], zS[64];
    int tid = threadIdx.x;      // 128
    int bh = blockIdx.y;
    int b = bh >> 2, h = bh & 3;
    int dst0 = blockIdx.x * 64;
    const float* sRow = s + (size_t)bh * NNODES;
    const float* dRow = d + (size_t)bh * NNODES;
    const float* xpB = xp + (size_t)b * NNODES * FG + h * OF;

    if (tid < 64) {
        int i = dst0 + tid;
        float dv = dRow[i];
        dS[tid] = dv;
        mS[tid] = lrelu(fmaxf(smax[bh * 2 + 1], sRow[i]) + dv);
    }
    int txf = tid & 7, tyd = tid >> 3;     // feat group (x4), dst group (x4)
    int ssrc = tid & 31, dgrp = tid >> 5;  // weight-compute mapping
    float acc[4][4] = {};
    float zacc[4] = {0.f, 0.f, 0.f, 0.f};

    for (int c = 0; c < 8; c++) {
        __syncthreads();
        #pragma unroll
        for (int q = 0; q < 2; q++) {
            int v = tid + q * 128;             // float4 index 0..255
            int src = v >> 3, feat = (v & 7) << 2;
            *(float4*)&xS[src * 32 + feat] =
                *(const float4*)&xpB[(size_t)(NSEC + c * 32 + src) * FG + feat];
        }
        if (tid < 32) sS[tid] = sRow[NSEC + c * 32 + tid];
        __syncthreads();
        float sv = sS[ssrc];
        #pragma unroll
        for (int r = 0; r < 16; r++) {
            int dd = dgrp * 16 + r;
            wS[dd * 33 + ssrc] = __expf(lrelu(sv + dS[dd]) - mS[dd]);
        }
        __syncthreads();
        #pragma unroll 8
        for (int k = 0; k < 32; k++) {
            float4 x = *(const float4*)&xS[k * 32 + 4 * txf];
            #pragma unroll
            for (int r = 0; r < 4; r++) {
                float w = wS[(4 * tyd + r) * 33 + k];
                acc[r][0] = fmaf(w, x.x, acc[r][0]);
                acc[r][1] = fmaf(w, x.y, acc[r][1]);
                acc[r][2] = fmaf(w, x.z, acc[r][2]);
                acc[r][3] = fmaf(w, x.w, acc[r][3]);
                if (txf == 0) zacc[r] += w;
            }
        }
    }
    __syncthreads();
    if (txf == 0) {
        #pragma unroll
        for (int r = 0; r < 4; r++) zS[4 * tyd + r] = zacc[r];
    }
    __syncthreads();
    float4 bv = *(const float4*)&bias[h * OF + 4 * txf];
    #pragma unroll
    for (int r = 0; r < 4; r++) {
        int li = 4 * tyd + r;
        int i = dst0 + li;
        float ws = __expf(lrelu(sRow[i] + dS[li]) - mS[li]);
        float4 xs = *(const float4*)&xpB[(size_t)i * FG + 4 * txf];
        float inv = 1.f / (zS[li] + ws);
        float4 o;
        o.x = fmaxf(fmaf(ws, xs.x, acc[r][0]) * inv + bv.x, 0.f);
        o.y = fmaxf(fmaf(ws, xs.y, acc[r][1]) * inv + bv.y, 0.f);
        o.z = fmaxf(fmaf(ws, xs.z, acc[r][2]) * inv + bv.z, 0.f);
        o.w = fmaxf(fmaf(ws, xs.w, acc[r][3]) * inv + bv.w, 0.f);
        *(float4*)&out[(size_t)b * outStrideB + (size_t)i * FG + h * OF + 4 * txf] = o;
    }
}

// ---------------- beam-destination aggregation, k-split partial pass -------
// 64 dst x 32 feat tile, 128 threads, 4x4 microtile, 256 of 1024 sec srcs.
__global__ void beam_agg_part_kernel(const float* __restrict__ xp, const float* __restrict__ s,
                                     const float* __restrict__ d, const float* __restrict__ smax,
                                     float* __restrict__ pfeat, float* __restrict__ pZ)
{
    __shared__ float xS[32 * 32];
    __shared__ float wS[64 * 33];
    __shared__ float sS[32];
    __shared__ float dS[64], mS[64];
    int tid = threadIdx.x;      // 128
    int bh = blockIdx.z;
    int b = bh >> 2, h = bh & 3;
    int dst0 = blockIdx.x * 64;
    int kblk = blockIdx.y;
    const float* sRow = s + (size_t)bh * NNODES;
    const float* dRow = d + (size_t)bh * NNODES;
    const float* xpB = xp + (size_t)b * NNODES * FG + h * OF;

    if (tid < 64) {
        int j = dst0 + tid;
        float dv = dRow[NSEC + j];
        dS[tid] = dv;
        float sP = sRow[NSEC + NPRIM + j];
        float sB = sRow[NSEC + j];
        mS[tid] = lrelu(fmaxf(fmaxf(smax[bh * 2], sP), sB) + dv);
    }
    int txf = tid & 7, tyd = tid >> 3;
    int ssrc = tid & 31, dgrp = tid >> 5;
    float acc[4][4] = {};
    float zacc[4] = {0.f, 0.f, 0.f, 0.f};

    for (int c = 0; c < 8; c++) {
        __syncthreads();
        #pragma unroll
        for (int q = 0; q < 2; q++) {
            int v = tid + q * 128;
            int src = v >> 3, feat = (v & 7) << 2;
            *(float4*)&xS[src * 32 + feat] =
                *(const float4*)&xpB[(size_t)(kblk * 256 + c * 32 + src) * FG + feat];
        }
        if (tid < 32) sS[tid] = sRow[kblk * 256 + c * 32 + tid];
        __syncthreads();
        float sv = sS[ssrc];
        #pragma unroll
        for (int r = 0; r < 16; r++) {
            int dd = dgrp * 16 + r;
            wS[dd * 33 + ssrc] = __expf(lrelu(sv + dS[dd]) - mS[dd]);
        }
        __syncthreads();
        #pragma unroll 8
        for (int k = 0; k < 32; k++) {
            float4 x = *(const float4*)&xS[k * 32 + 4 * txf];
            #pragma unroll
            for (int r = 0; r < 4; r++) {
                float w = wS[(4 * tyd + r) * 33 + k];
                acc[r][0] = fmaf(w, x.x, acc[r][0]);
                acc[r][1] = fmaf(w, x.y, acc[r][1]);
                acc[r][2] = fmaf(w, x.z, acc[r][2]);
                acc[r][3] = fmaf(w, x.w, acc[r][3]);
                if (txf == 0) zacc[r] += w;
            }
        }
    }
    size_t pbase = (size_t)(bh * 4 + kblk) * 256;
    #pragma unroll
    for (int r = 0; r < 4; r++) {
        int j = dst0 + 4 * tyd + r;
        float4 o = {acc[r][0], acc[r][1], acc[r][2], acc[r][3]};
        *(float4*)&pfeat[(pbase + j) * 32 + 4 * txf] = o;
        if (txf == 0) pZ[pbase + j] = zacc[r];
    }
}

// ---------------- beam combine (fixed-order deterministic) -----------------
__global__ void beam_combine_kernel(const float* __restrict__ xp, const float* __restrict__ s,
                                    const float* __restrict__ d, const float* __restrict__ smax,
                                    const float* __restrict__ pfeat, const float* __restrict__ pZ,
                                    const float* __restrict__ bias, float* __restrict__ out)
{
    int tid = threadIdx.x, warp = tid >> 5, lane = tid & 31;
    int bh = blockIdx.y, b = bh >> 2, h = bh & 3;
    int j = blockIdx.x * 8 + warp;
    const float* sRow = s + (size_t)bh * NNODES;
    const float* dRow = d + (size_t)bh * NNODES;
    float dv = dRow[NSEC + j];
    float sP = sRow[NSEC + NPRIM + j];
    float sB = sRow[NSEC + j];
    float m = lrelu(fmaxf(fmaxf(smax[bh * 2], sP), sB) + dv);   // identical to partial pass
    float wp = __expf(lrelu(sP + dv) - m);
    float ws = __expf(lrelu(sB + dv) - m);
    size_t p0 = (size_t)bh * 4 * 256 + j;
    float Z = ((pZ[p0] + pZ[p0 + 256]) + pZ[p0 + 512]) + pZ[p0 + 768] + wp + ws;
    float acc = ((pfeat[p0 * 32 + lane] + pfeat[(p0 + 256) * 32 + lane])
                 + pfeat[(p0 + 512) * 32 + lane]) + pfeat[(p0 + 768) * 32 + lane];
    const float* xpB = xp + (size_t)b * NNODES * FG + h * OF;
    acc = fmaf(wp, xpB[(size_t)(NSEC + NPRIM + j) * FG + lane], acc);
    acc = fmaf(ws, xpB[(size_t)(NSEC + j) * FG + lane], acc);
    float v = acc / Z + bias[h * OF + lane];
    out[(size_t)b * NNODES * FG + (size_t)(NSEC + j) * FG + h * OF + lane] = fmaxf(v, 0.f);
}

// ---------------- ratio + scale/threshold ----------------------------------
__global__ void ratio_kernel(const float* __restrict__ pP, const float* __restrict__ pT,
                             const float* __restrict__ part, float* __restrict__ ratio)
{
    int warp = threadIdx.x >> 5, lane = threadIdx.x & 31;
    if (warp >= BB) return;
    float ps = part[warp * 32 + lane];     // 32 partials per batch (16 by * 2 bx)
    ps = warpSum(ps);
    float pps = 0.f;
    #pragma unroll
    for (int k = 0; k < 8; k++) pps += pP[warp * 256 + lane + 32 * k];
    pps = warpSum(pps);
    if (lane == 0) {
        float num = fmaxf((*pT) - pps, 0.f);
        float r = num / (ps + 1e-5f);
        ratio[warp] = fminf(r, 1.f);
    }
}

__global__ void scale_kernel(float* __restrict__ C, const float* __restrict__ ratio)
{
    int idx = blockIdx.x * 256 + threadIdx.x;
    int b = idx >> 18;
    float v = C[idx] * ratio[b];
    C[idx] = (v > 0.001f) ? v : 0.f;
}

// ---------------- launch ----------------------------------------------------
extern "C" void kernel_launch(void* const* d_in, const int* in_sizes, int n_in,
                              void* d_out, int out_size)
{
    const float* h   = (const float*)d_in[0];
    const float* pP  = (const float*)d_in[1];
    const float* pT  = (const float*)d_in[2];
    const float* W0  = (const float*)d_in[3];
    const float* b0  = (const float*)d_in[4];
    const float* as0 = (const float*)d_in[5];
    const float* ad0 = (const float*)d_in[6];
    const float* W1  = (const float*)d_in[7];
    const float* b1  = (const float*)d_in[8];
    const float* as1 = (const float*)d_in[9];
    const float* ad1 = (const float*)d_in[10];
    const float* Wf0 = (const float*)d_in[11];
    const float* bf0 = (const float*)d_in[12];
    const float* Wf1 = (const float*)d_in[13];
    const float* bf1 = (const float*)d_in[14];
    float* out = (float*)d_out;

    float* base = nullptr;
    cudaGetSymbolAddress((void**)&base, g_scratch);
    float* xp1   = base;                 // 786432
    float* x1    = xp1 + 786432;         // 786432
    float* xp2   = x1 + 786432;          // 786432
    float* hg    = xp2 + 786432;         // 524288
    float* z     = hg + 524288;          // 1048576
    float* s1    = z + 1048576;          // 24576
    float* d1    = s1 + 24576;
    float* s2    = d1 + 24576;
    float* d2    = s2 + 24576;
    float* smax1 = d2 + 24576;           // 32
    float* smax2 = smax1 + 32;           // 32
    float* pfeat = smax2 + 32;           // 524288
    float* pZ    = pfeat + 524288;       // 16384
    float* part  = pZ + 16384;           // 128
    float* ratio = part + 128;           // 4

    // Layer 1 (sd fused into GEMM epilogue)
    gemm_kernel<<<dim3(1, 96), 256>>>(h, W0, nullptr, xp1, BB * NNODES, FG, FG, 0,
                                      nullptr, as0, ad0, s1, d1);
    smax_kernel<<<16, 256>>>(s1, smax1);
    sec_agg2_kernel<<<dim3(16, 16), 128>>>(xp1, s1, d1, smax1, b0, x1, NNODES * FG);
    beam_agg_part_kernel<<<dim3(4, 4, 16), 128>>>(xp1, s1, d1, smax1, pfeat, pZ);
    beam_combine_kernel<<<dim3(32, 16), 256>>>(xp1, s1, d1, smax1, pfeat, pZ, b0, x1);

    // Layer 2 (only sec destinations needed downstream)
    gemm_kernel<<<dim3(1, 96), 256>>>(x1, W1, nullptr, xp2, BB * NNODES, FG, FG, 0,
                                      nullptr, as1, ad1, s2, d2);
    smax_kernel<<<16, 256>>>(s2, smax2);
    sec_agg2_kernel<<<dim3(16, 16), 128>>>(xp2, s2, d2, smax2, b1, hg, NSEC * FG);

    // FC stack
    gemm_kernel<<<dim3(2, 64), 256>>>(hg, Wf0, bf0, z, BB * NSEC, 256, FG, 1,
                                      nullptr, nullptr, nullptr, nullptr, nullptr);
    gemm_kernel<<<dim3(2, 64), 256>>>(z, Wf1, bf1, out, BB * NSEC, 256, 256, 1,
                                      part, nullptr, nullptr, nullptr, nullptr);

    // Power ratio + threshold
    ratio_kernel<<<1, 128>>>(pP, pT, part, ratio);
    scale_kernel<<<4096, 256>>>(out, ratio);
}

// round 4
// speedup vs baseline: 1.3597x; 1.3597x over previous
#include <cuda_runtime.h>

#define BB 4
#define NSEC 1024
#define NPRIM 256
#define NNODES 1536
#define NH 4
#define OF 32
#define FG 128

// ---------------- scratch (static device memory, no allocs) ----------------
__device__ float g_scratch[4700000];

__device__ __forceinline__ float lrelu(float x) { return x > 0.f ? x : 0.2f * x; }
__device__ __forceinline__ float warpSum(float v) {
    #pragma unroll
    for (int o = 16; o > 0; o >>= 1) v += __shfl_xor_sync(0xffffffffu, v, o);
    return v;
}

// ---------------- GEMM: C[M,N] = A[M,K] @ B[K,N] (+bias)(+relu)(+sd) -------
// 64x64 tile, BK=16, 256 threads, 4x4 microtile. Optional fused per-(row,head)
// attention scalars s,d (xp GEMMs; requires N==128) and per-block partials.
__global__ void gemm_kernel(const float* __restrict__ A, const float* __restrict__ B,
                            const float* __restrict__ bias, float* __restrict__ C,
                            int M, int N, int K, int doRelu, float* __restrict__ part,
                            const float* __restrict__ a_s, const float* __restrict__ a_d,
                            float* __restrict__ s, float* __restrict__ d)
{
    __shared__ float As[16][64];
    __shared__ float Bs[16][64];
    int tid = threadIdx.x;
    int tx = tid & 15, ty = tid >> 4;
    int m0 = blockIdx.y * 64, n0 = blockIdx.x * 64;
    float acc[4][4] = {};
    int am = tid >> 2, ak = (tid & 3) << 2;
    int bk = tid >> 4, bn = (tid & 15) << 2;

    for (int k0 = 0; k0 < K; k0 += 16) {
        float4 a = *(const float4*)(A + (size_t)(m0 + am) * K + k0 + ak);
        As[ak + 0][am] = a.x; As[ak + 1][am] = a.y;
        As[ak + 2][am] = a.z; As[ak + 3][am] = a.w;
        *(float4*)&Bs[bk][bn] = *(const float4*)(B + (size_t)(k0 + bk) * N + n0 + bn);
        __syncthreads();
        #pragma unroll
        for (int k = 0; k < 16; k++) {
            float4 a4 = *(const float4*)&As[k][ty << 2];
            float4 b4 = *(const float4*)&Bs[k][tx << 2];
            float av[4] = {a4.x, a4.y, a4.z, a4.w};
            float bv[4] = {b4.x, b4.y, b4.z, b4.w};
            #pragma unroll
            for (int i = 0; i < 4; i++)
                #pragma unroll
                for (int j = 0; j < 4; j++)
                    acc[i][j] = fmaf(av[i], bv[j], acc[i][j]);
        }
        __syncthreads();
    }

    float bsum = 0.f;
    #pragma unroll
    for (int i = 0; i < 4; i++) {
        int row = m0 + (ty << 2) + i;
        #pragma unroll
        for (int j = 0; j < 4; j++) {
            int col = n0 + (tx << 2) + j;
            float v = acc[i][j];
            if (bias) v += bias[col];
            if (doRelu) v = fmaxf(v, 0.f);
            C[(size_t)row * N + col] = v;
            bsum += v;
        }
    }

    // Fused attention scalars (xp GEMMs, N==128): head h owns 32 contiguous
    // cols, fully inside this 64-col tile. 8 threads (tx bits 0..2) cover it.
    if (s) {
        int h = (n0 >> 5) + (tx >> 3);
        const float* asr = a_s + h * OF + (tx & 7) * 4;
        const float* adr = a_d + h * OF + (tx & 7) * 4;
        #pragma unroll
        for (int i = 0; i < 4; i++) {
            float ss = 0.f, dd = 0.f;
            #pragma unroll
            for (int j = 0; j < 4; j++) {
                ss = fmaf(acc[i][j], asr[j], ss);
                dd = fmaf(acc[i][j], adr[j], dd);
            }
            ss += __shfl_xor_sync(0xffffffffu, ss, 1);
            ss += __shfl_xor_sync(0xffffffffu, ss, 2);
            ss += __shfl_xor_sync(0xffffffffu, ss, 4);
            dd += __shfl_xor_sync(0xffffffffu, dd, 1);
            dd += __shfl_xor_sync(0xffffffffu, dd, 2);
            dd += __shfl_xor_sync(0xffffffffu, dd, 4);
            if ((tx & 7) == 0) {
                int row = m0 + (ty << 2) + i;
                int b = row / NNODES;
                int n = row - b * NNODES;
                s[(size_t)(b * NH + h) * NNODES + n] = ss;
                d[(size_t)(b * NH + h) * NNODES + n] = dd;
            }
        }
    }

    if (part) {
        __shared__ float red[256];
        red[tid] = bsum;
        __syncthreads();
        #pragma unroll
        for (int st = 128; st > 0; st >>= 1) {
            if (tid < st) red[tid] += red[tid + st];
            __syncthreads();
        }
        if (tid == 0) part[blockIdx.y * gridDim.x + blockIdx.x] = red[0];
    }
}

// ---------------- segment max of s over sec range & beam range -------------
__global__ void smax_kernel(const float* __restrict__ s, float* __restrict__ smax)
{
    __shared__ float red[256];
    int bh = blockIdx.x, tid = threadIdx.x;
    const float* sRow = s + (size_t)bh * NNODES;
    float m = fmaxf(fmaxf(sRow[tid], sRow[tid + 256]),
                    fmaxf(sRow[tid + 512], sRow[tid + 768]));
    red[tid] = m;
    __syncthreads();
    #pragma unroll
    for (int st = 128; st > 0; st >>= 1) {
        if (tid < st) red[tid] = fmaxf(red[tid], red[tid + st]);
        __syncthreads();
    }
    if (tid == 0) smax[bh * 2] = red[0];
    __syncthreads();
    red[tid] = sRow[NSEC + tid];
    __syncthreads();
    #pragma unroll
    for (int st = 128; st > 0; st >>= 1) {
        if (tid < st) red[tid] = fmaxf(red[tid], red[tid + st]);
        __syncthreads();
    }
    if (tid == 0) smax[bh * 2 + 1] = red[0];
}

// ---------------- sec-destination aggregation ------------------------------
// 64 dst x 32 feat tile, 256 threads = 2 warp-groups; group g accumulates
// source chunks g*4..g*4+3 (of 8x32 beam srcs); fixed-order SMEM combine.
__global__ void sec_agg3_kernel(const float* __restrict__ xp, const float* __restrict__ s,
                                const float* __restrict__ d, const float* __restrict__ smax,
                                const float* __restrict__ bias, float* __restrict__ out,
                                int outStrideB)
{
    __shared__ float xS[2][32 * 32];
    __shared__ float wS[2][64 * 33];
    __shared__ float sS[2][32];
    __shared__ float dS[64], mS[64];
    __shared__ float comb[64 * 32];
    __shared__ float zS[2][64];
    int tid = threadIdx.x;
    int grp = tid >> 7, lt = tid & 127;
    int bh = blockIdx.y;
    int b = bh >> 2, h = bh & 3;
    int dst0 = blockIdx.x * 64;
    const float* sRow = s + (size_t)bh * NNODES;
    const float* dRow = d + (size_t)bh * NNODES;
    const float* xpB = xp + (size_t)b * NNODES * FG + h * OF;

    if (tid < 64) {
        int i = dst0 + tid;
        float dv = dRow[i];
        dS[tid] = dv;
        mS[tid] = lrelu(fmaxf(smax[bh * 2 + 1], sRow[i]) + dv);
    }
    int txf = lt & 7, tyd = lt >> 3;
    int ssrc = lt & 31, dgrp = lt >> 5;
    float acc[4][4] = {};
    float zacc[4] = {0.f, 0.f, 0.f, 0.f};

    #pragma unroll 1
    for (int c = 0; c < 4; c++) {
        int chunk = grp * 4 + c;
        __syncthreads();
        #pragma unroll
        for (int q = 0; q < 2; q++) {
            int v = lt + q * 128;
            int src = v >> 3, feat = (v & 7) << 2;
            *(float4*)&xS[grp][src * 32 + feat] =
                *(const float4*)&xpB[(size_t)(NSEC + chunk * 32 + src) * FG + feat];
        }
        if (lt < 32) sS[grp][lt] = sRow[NSEC + chunk * 32 + lt];
        __syncthreads();
        float sv = sS[grp][ssrc];
        #pragma unroll
        for (int r = 0; r < 16; r++) {
            int dd = dgrp * 16 + r;
            wS[grp][dd * 33 + ssrc] = __expf(lrelu(sv + dS[dd]) - mS[dd]);
        }
        __syncthreads();
        #pragma unroll 8
        for (int k = 0; k < 32; k++) {
            float4 x = *(const float4*)&xS[grp][k * 32 + 4 * txf];
            #pragma unroll
            for (int r = 0; r < 4; r++) {
                float w = wS[grp][(4 * tyd + r) * 33 + k];
                acc[r][0] = fmaf(w, x.x, acc[r][0]);
                acc[r][1] = fmaf(w, x.y, acc[r][1]);
                acc[r][2] = fmaf(w, x.z, acc[r][2]);
                acc[r][3] = fmaf(w, x.w, acc[r][3]);
                if (txf == 0) zacc[r] += w;
            }
        }
    }
    __syncthreads();
    if (txf == 0) {
        #pragma unroll
        for (int r = 0; r < 4; r++) zS[grp][4 * tyd + r] = zacc[r];
    }
    if (grp == 1) {
        #pragma unroll
        for (int r = 0; r < 4; r++) {
            float4 o = {acc[r][0], acc[r][1], acc[r][2], acc[r][3]};
            *(float4*)&comb[(4 * tyd + r) * 32 + 4 * txf] = o;
        }
    }
    __syncthreads();
    if (grp == 0) {
        float4 bv = *(const float4*)&bias[h * OF + 4 * txf];
        #pragma unroll
        for (int r = 0; r < 4; r++) {
            int li = 4 * tyd + r;
            int i = dst0 + li;
            float4 c4 = *(const float4*)&comb[li * 32 + 4 * txf];
            float ws = __expf(lrelu(sRow[i] + dS[li]) - mS[li]);
            float4 xs = *(const float4*)&xpB[(size_t)i * FG + 4 * txf];
            float inv = 1.f / (zS[0][li] + zS[1][li] + ws);
            float4 o;
            o.x = fmaxf((fmaf(ws, xs.x, acc[r][0] + c4.x)) * inv + bv.x, 0.f);
            o.y = fmaxf((fmaf(ws, xs.y, acc[r][1] + c4.y)) * inv + bv.y, 0.f);
            o.z = fmaxf((fmaf(ws, xs.z, acc[r][2] + c4.z)) * inv + bv.z, 0.f);
            o.w = fmaxf((fmaf(ws, xs.w, acc[r][3] + c4.w)) * inv + bv.w, 0.f);
            *(float4*)&out[(size_t)b * outStrideB + (size_t)i * FG + h * OF + 4 * txf] = o;
        }
    }
}

// ---------------- beam-destination aggregation, k-split partial pass -------
// 64 dst x 32 feat tile, 256 thr (2 warp-groups over 8 chunks of this kblk's
// 256 sec srcs), fixed-order combine, partial output.
__global__ void beam_agg_part3_kernel(const float* __restrict__ xp, const float* __restrict__ s,
                                      const float* __restrict__ d, const float* __restrict__ smax,
                                      float* __restrict__ pfeat, float* __restrict__ pZ)
{
    __shared__ float xS[2][32 * 32];
    __shared__ float wS[2][64 * 33];
    __shared__ float sS[2][32];
    __shared__ float dS[64], mS[64];
    __shared__ float comb[64 * 32];
    __shared__ float zS[2][64];
    int tid = threadIdx.x;
    int grp = tid >> 7, lt = tid & 127;
    int bh = blockIdx.z;
    int b = bh >> 2, h = bh & 3;
    int dst0 = blockIdx.x * 64;
    int kblk = blockIdx.y;
    const float* sRow = s + (size_t)bh * NNODES;
    const float* dRow = d + (size_t)bh * NNODES;
    const float* xpB = xp + (size_t)b * NNODES * FG + h * OF;

    if (tid < 64) {
        int j = dst0 + tid;
        float dv = dRow[NSEC + j];
        dS[tid] = dv;
        float sP = sRow[NSEC + NPRIM + j];
        float sB = sRow[NSEC + j];
        mS[tid] = lrelu(fmaxf(fmaxf(smax[bh * 2], sP), sB) + dv);
    }
    int txf = lt & 7, tyd = lt >> 3;
    int ssrc = lt & 31, dgrp = lt >> 5;
    float acc[4][4] = {};
    float zacc[4] = {0.f, 0.f, 0.f, 0.f};

    #pragma unroll 1
    for (int c = 0; c < 4; c++) {
        int chunk = grp * 4 + c;
        __syncthreads();
        #pragma unroll
        for (int q = 0; q < 2; q++) {
            int v = lt + q * 128;
            int src = v >> 3, feat = (v & 7) << 2;
            *(float4*)&xS[grp][src * 32 + feat] =
                *(const float4*)&xpB[(size_t)(kblk * 256 + chunk * 32 + src) * FG + feat];
        }
        if (lt < 32) sS[grp][lt] = sRow[kblk * 256 + chunk * 32 + lt];
        __syncthreads();
        float sv = sS[grp][ssrc];
        #pragma unroll
        for (int r = 0; r < 16; r++) {
            int dd = dgrp * 16 + r;
            wS[grp][dd * 33 + ssrc] = __expf(lrelu(sv + dS[dd]) - mS[dd]);
        }
        __syncthreads();
        #pragma unroll 8
        for (int k = 0; k < 32; k++) {
            float4 x = *(const float4*)&xS[grp][k * 32 + 4 * txf];
            #pragma unroll
            for (int r = 0; r < 4; r++) {
                float w = wS[grp][(4 * tyd + r) * 33 + k];
                acc[r][0] = fmaf(w, x.x, acc[r][0]);
                acc[r][1] = fmaf(w, x.y, acc[r][1]);
                acc[r][2] = fmaf(w, x.z, acc[r][2]);
                acc[r][3] = fmaf(w, x.w, acc[r][3]);
                if (txf == 0) zacc[r] += w;
            }
        }
    }
    __syncthreads();
    if (txf == 0) {
        #pragma unroll
        for (int r = 0; r < 4; r++) zS[grp][4 * tyd + r] = zacc[r];
    }
    if (grp == 1) {
        #pragma unroll
        for (int r = 0; r < 4; r++) {
            float4 o = {acc[r][0], acc[r][1], acc[r][2], acc[r][3]};
            *(float4*)&comb[(4 * tyd + r) * 32 + 4 * txf] = o;
        }
    }
    __syncthreads();
    if (grp == 0) {
        size_t pbase = (size_t)(bh * 4 + kblk) * 256;
        #pragma unroll
        for (int r = 0; r < 4; r++) {
            int li = 4 * tyd + r;
            int j = dst0 + li;
            float4 c4 = *(const float4*)&comb[li * 32 + 4 * txf];
            float4 o = {acc[r][0] + c4.x, acc[r][1] + c4.y,
                        acc[r][2] + c4.z, acc[r][3] + c4.w};
            *(float4*)&pfeat[(pbase + j) * 32 + 4 * txf] = o;
            if (txf == 0) pZ[pbase + j] = zS[0][li] + zS[1][li];
        }
    }
}

// ---------------- beam combine (fixed-order deterministic) -----------------
__global__ void beam_combine_kernel(const float* __restrict__ xp, const float* __restrict__ s,
                                    const float* __restrict__ d, const float* __restrict__ smax,
                                    const float* __restrict__ pfeat, const float* __restrict__ pZ,
                                    const float* __restrict__ bias, float* __restrict__ out)
{
    int tid = threadIdx.x, warp = tid >> 5, lane = tid & 31;
    int bh = blockIdx.y, b = bh >> 2, h = bh & 3;
    int j = blockIdx.x * 8 + warp;
    const float* sRow = s + (size_t)bh * NNODES;
    const float* dRow = d + (size_t)bh * NNODES;
    float dv = dRow[NSEC + j];
    float sP = sRow[NSEC + NPRIM + j];
    float sB = sRow[NSEC + j];
    float m = lrelu(fmaxf(fmaxf(smax[bh * 2], sP), sB) + dv);   // identical to partial pass
    float wp = __expf(lrelu(sP + dv) - m);
    float ws = __expf(lrelu(sB + dv) - m);
    size_t p0 = (size_t)bh * 4 * 256 + j;
    float Z = ((pZ[p0] + pZ[p0 + 256]) + pZ[p0 + 512]) + pZ[p0 + 768] + wp + ws;
    float acc = ((pfeat[p0 * 32 + lane] + pfeat[(p0 + 256) * 32 + lane])
                 + pfeat[(p0 + 512) * 32 + lane]) + pfeat[(p0 + 768) * 32 + lane];
    const float* xpB = xp + (size_t)b * NNODES * FG + h * OF;
    acc = fmaf(wp, xpB[(size_t)(NSEC + NPRIM + j) * FG + lane], acc);
    acc = fmaf(ws, xpB[(size_t)(NSEC + j) * FG + lane], acc);
    float v = acc / Z + bias[h * OF + lane];
    out[(size_t)b * NNODES * FG + (size_t)(NSEC + j) * FG + h * OF + lane] = fmaxf(v, 0.f);
}

// ---------------- ratio + scale/threshold ----------------------------------
__global__ void ratio_kernel(const float* __restrict__ pP, const float* __restrict__ pT,
                             const float* __restrict__ part, float* __restrict__ ratio)
{
    int warp = threadIdx.x >> 5, lane = threadIdx.x & 31;
    if (warp >= BB) return;
    float ps = part[warp * 64 + lane] + part[warp * 64 + 32 + lane];
    ps = warpSum(ps);
    float pps = 0.f;
    #pragma unroll
    for (int k = 0; k < 8; k++) pps += pP[warp * 256 + lane + 32 * k];
    pps = warpSum(pps);
    if (lane == 0) {
        float num = fmaxf((*pT) - pps, 0.f);
        float r = num / (ps + 1e-5f);
        ratio[warp] = fminf(r, 1.f);
    }
}

__global__ void scale_kernel(float* __restrict__ C, const float* __restrict__ ratio)
{
    int idx = blockIdx.x * 256 + threadIdx.x;
    int b = idx >> 18;
    float v = C[idx] * ratio[b];
    C[idx] = (v > 0.001f) ? v : 0.f;
}

// ---------------- launch ----------------------------------------------------
extern "C" void kernel_launch(void* const* d_in, const int* in_sizes, int n_in,
                              void* d_out, int out_size)
{
    const float* h   = (const float*)d_in[0];
    const float* pP  = (const float*)d_in[1];
    const float* pT  = (const float*)d_in[2];
    const float* W0  = (const float*)d_in[3];
    const float* b0  = (const float*)d_in[4];
    const float* as0 = (const float*)d_in[5];
    const float* ad0 = (const float*)d_in[6];
    const float* W1  = (const float*)d_in[7];
    const float* b1  = (const float*)d_in[8];
    const float* as1 = (const float*)d_in[9];
    const float* ad1 = (const float*)d_in[10];
    const float* Wf0 = (const float*)d_in[11];
    const float* bf0 = (const float*)d_in[12];
    const float* Wf1 = (const float*)d_in[13];
    const float* bf1 = (const float*)d_in[14];
    float* out = (float*)d_out;

    float* base = nullptr;
    cudaGetSymbolAddress((void**)&base, g_scratch);
    float* xp1   = base;                 // 786432
    float* x1    = xp1 + 786432;         // 786432
    float* xp2   = x1 + 786432;          // 786432
    float* hg    = xp2 + 786432;         // 524288
    float* z     = hg + 524288;          // 1048576
    float* s1    = z + 1048576;          // 24576
    float* d1    = s1 + 24576;
    float* s2    = d1 + 24576;
    float* d2    = s2 + 24576;
    float* smax1 = d2 + 24576;           // 32
    float* smax2 = smax1 + 32;           // 32
    float* pfeat = smax2 + 32;           // 524288
    float* pZ    = pfeat + 524288;       // 16384
    float* part  = pZ + 16384;           // 256
    float* ratio = part + 256;           // 4

    // Layer 1 (sd fused into GEMM epilogue)
    gemm_kernel<<<dim3(2, 96), 256>>>(h, W0, nullptr, xp1, BB * NNODES, FG, FG, 0,
                                      nullptr, as0, ad0, s1, d1);
    smax_kernel<<<16, 256>>>(s1, smax1);
    sec_agg3_kernel<<<dim3(16, 16), 256>>>(xp1, s1, d1, smax1, b0, x1, NNODES * FG);
    beam_agg_part3_kernel<<<dim3(4, 4, 16), 256>>>(xp1, s1, d1, smax1, pfeat, pZ);
    beam_combine_kernel<<<dim3(32, 16), 256>>>(xp1, s1, d1, smax1, pfeat, pZ, b0, x1);

    // Layer 2 (only sec destinations needed downstream)
    gemm_kernel<<<dim3(2, 96), 256>>>(x1, W1, nullptr, xp2, BB * NNODES, FG, FG, 0,
                                      nullptr, as1, ad1, s2, d2);
    smax_kernel<<<16, 256>>>(s2, smax2);
    sec_agg3_kernel<<<dim3(16, 16), 256>>>(xp2, s2, d2, smax2, b1, hg, NSEC * FG);

    // FC stack
    gemm_kernel<<<dim3(4, 64), 256>>>(hg, Wf0, bf0, z, BB * NSEC, 256, FG, 1,
                                      nullptr, nullptr, nullptr, nullptr, nullptr);
    gemm_kernel<<<dim3(4, 64), 256>>>(z, Wf1, bf1, out, BB * NSEC, 256, 256, 1,
                                      part, nullptr, nullptr, nullptr, nullptr);

    // Power ratio + threshold
    ratio_kernel<<<1, 128>>>(pP, pT, part, ratio);
    scale_kernel<<<4096, 256>>>(out, ratio);
}

// round 5
// speedup vs baseline: 1.5971x; 1.1746x over previous
#include <cuda_runtime.h>

#define BB 4
#define NSEC 1024
#define NPRIM 256
#define NNODES 1536
#define NH 4
#define OF 32
#define FG 128

// ---------------- scratch (static device memory, no allocs) ----------------
__device__ float g_scratch[4700000];

__device__ __forceinline__ float lrelu(float x) { return x > 0.f ? x : 0.2f * x; }
__device__ __forceinline__ float warpSum(float v) {
    #pragma unroll
    for (int o = 16; o > 0; o >>= 1) v += __shfl_xor_sync(0xffffffffu, v, o);
    return v;
}
// monotone float<->uint encoding for deterministic atomicMax on floats
__device__ __forceinline__ unsigned encf(float f) {
    unsigned u = __float_as_uint(f);
    return (u & 0x80000000u) ? ~u : (u | 0x80000000u);
}
__device__ __forceinline__ float decf(unsigned u) {
    return (u & 0x80000000u) ? __uint_as_float(u ^ 0x80000000u) : __uint_as_float(~u);
}

// ---------------- GEMM: C = A@B (+bias)(+relu)(+fused sd & segment-max) ----
// 64x64 tile, BK=16, 256 threads, 4x4 microtile, double-buffered SMEM.
// Row-tile remap: by -> m0 = (by/tilesKeep)*tilesTotal*64 + (by%tilesKeep)*64
// (lets gemm2 skip prim rows). When s!=null (xp GEMMs, N==128): computes
// per-(row,head) attention scalars s,d and atomically builds encoded segment
// maxes of s over the sec range (slot 0) and beam range (slot 1).
__global__ void gemm_kernel(const float* __restrict__ A, const float* __restrict__ B,
                            const float* __restrict__ bias, float* __restrict__ C,
                            int N, int K, int tilesKeep, int tilesTotal, int doRelu,
                            float* __restrict__ part,
                            const float* __restrict__ a_s, const float* __restrict__ a_d,
                            float* __restrict__ s, float* __restrict__ d,
                            unsigned* __restrict__ smaxu)
{
    __shared__ float As[2][16][64];
    __shared__ float Bs[2][16][64];
    int tid = threadIdx.x;
    int tx = tid & 15, ty = tid >> 4;
    int by = blockIdx.y;
    int bt = by / tilesKeep;
    int m0 = bt * tilesTotal * 64 + (by - bt * tilesKeep) * 64;
    int n0 = blockIdx.x * 64;
    float acc[4][4] = {};
    int am = tid >> 2, ak = (tid & 3) << 2;
    int bk = tid >> 4, bn = (tid & 15) << 2;
    const float* Abase = A + (size_t)(m0 + am) * K + ak;
    const float* Bbase = B + (size_t)bk * N + n0 + bn;

    // prologue: tile 0
    {
        float4 a = *(const float4*)(Abase);
        float4 bb = *(const float4*)(Bbase);
        As[0][ak + 0][am] = a.x; As[0][ak + 1][am] = a.y;
        As[0][ak + 2][am] = a.z; As[0][ak + 3][am] = a.w;
        *(float4*)&Bs[0][bk][bn] = bb;
    }
    __syncthreads();
    int nT = K >> 4;
    #pragma unroll 2
    for (int it = 1; it < nT; it++) {
        float4 a2 = *(const float4*)(Abase + it * 16);
        float4 b2 = *(const float4*)(Bbase + (size_t)it * 16 * N);
        int pb = (it - 1) & 1;
        #pragma unroll
        for (int k = 0; k < 16; k++) {
            float4 a4 = *(const float4*)&As[pb][k][ty << 2];
            float4 b4 = *(const float4*)&Bs[pb][k][tx << 2];
            float av[4] = {a4.x, a4.y, a4.z, a4.w};
            float bv[4] = {b4.x, b4.y, b4.z, b4.w};
            #pragma unroll
            for (int i = 0; i < 4; i++)
                #pragma unroll
                for (int j = 0; j < 4; j++)
                    acc[i][j] = fmaf(av[i], bv[j], acc[i][j]);
        }
        int cb = it & 1;
        As[cb][ak + 0][am] = a2.x; As[cb][ak + 1][am] = a2.y;
        As[cb][ak + 2][am] = a2.z; As[cb][ak + 3][am] = a2.w;
        *(float4*)&Bs[cb][bk][bn] = b2;
        __syncthreads();
    }
    {
        int pb = (nT - 1) & 1;
        #pragma unroll
        for (int k = 0; k < 16; k++) {
            float4 a4 = *(const float4*)&As[pb][k][ty << 2];
            float4 b4 = *(const float4*)&Bs[pb][k][tx << 2];
            float av[4] = {a4.x, a4.y, a4.z, a4.w};
            float bv[4] = {b4.x, b4.y, b4.z, b4.w};
            #pragma unroll
            for (int i = 0; i < 4; i++)
                #pragma unroll
                for (int j = 0; j < 4; j++)
                    acc[i][j] = fmaf(av[i], bv[j], acc[i][j]);
        }
    }

    float bsum = 0.f;
    #pragma unroll
    for (int i = 0; i < 4; i++) {
        int row = m0 + (ty << 2) + i;
        #pragma unroll
        for (int j = 0; j < 4; j++) {
            int col = n0 + (tx << 2) + j;
            float v = acc[i][j];
            if (bias) v += bias[col];
            if (doRelu) v = fmaxf(v, 0.f);
            C[(size_t)row * N + col] = v;
            bsum += v;
        }
    }

    // Fused attention scalars + encoded segment-max (xp GEMMs, N==128).
    if (s) {
        __shared__ float redm[2][16];
        int b_blk = m0 / NNODES;
        int nb = m0 - b_blk * NNODES;              // row-in-batch of this tile
        int type = nb < NSEC ? 0 : (nb < NSEC + NPRIM ? 1 : 2);
        int h = (n0 >> 5) + (tx >> 3);
        const float* asr = a_s + h * OF + (tx & 7) * 4;
        const float* adr = a_d + h * OF + (tx & 7) * 4;
        float lmax = -1e30f;
        #pragma unroll
        for (int i = 0; i < 4; i++) {
            float ss = 0.f, dd = 0.f;
            #pragma unroll
            for (int j = 0; j < 4; j++) {
                ss = fmaf(acc[i][j], asr[j], ss);
                dd = fmaf(acc[i][j], adr[j], dd);
            }
            ss += __shfl_xor_sync(0xffffffffu, ss, 1);
            ss += __shfl_xor_sync(0xffffffffu, ss, 2);
            ss += __shfl_xor_sync(0xffffffffu, ss, 4);
            dd += __shfl_xor_sync(0xffffffffu, dd, 1);
            dd += __shfl_xor_sync(0xffffffffu, dd, 2);
            dd += __shfl_xor_sync(0xffffffffu, dd, 4);
            if ((tx & 7) == 0) {
                int row = m0 + (ty << 2) + i;
                int n = row - b_blk * NNODES;
                s[(size_t)(b_blk * NH + h) * NNODES + n] = ss;
                d[(size_t)(b_blk * NH + h) * NNODES + n] = dd;
                lmax = fmaxf(lmax, ss);
            }
        }
        if ((tx & 7) == 0) redm[tx >> 3][ty] = lmax;
        __syncthreads();
        if (tid < 2 && type < 2) {
            float m = redm[tid][0];
            #pragma unroll
            for (int q = 1; q < 16; q++) m = fmaxf(m, redm[tid][q]);
            int hh = (n0 >> 5) + tid;
            atomicMax(&smaxu[(b_blk * NH + hh) * 2 + type], encf(m));
        }
    }

    if (part) {
        __shared__ float red[256];
        red[tid] = bsum;
        __syncthreads();
        #pragma unroll
        for (int st = 128; st > 0; st >>= 1) {
            if (tid < st) red[tid] += red[tid + st];
            __syncthreads();
        }
        if (tid == 0) part[blockIdx.y * gridDim.x + blockIdx.x] = red[0];
    }
}

// ---------------- sec-destination aggregation ------------------------------
__global__ void sec_agg3_kernel(const float* __restrict__ xp, const float* __restrict__ s,
                                const float* __restrict__ d, const unsigned* __restrict__ smaxu,
                                const float* __restrict__ bias, float* __restrict__ out,
                                int outStrideB)
{
    __shared__ float xS[2][32 * 32];
    __shared__ float wS[2][64 * 33];
    __shared__ float sS[2][32];
    __shared__ float dS[64], mS[64];
    __shared__ float comb[64 * 32];
    __shared__ float zS[2][64];
    int tid = threadIdx.x;
    int grp = tid >> 7, lt = tid & 127;
    int bh = blockIdx.y;
    int b = bh >> 2, h = bh & 3;
    int dst0 = blockIdx.x * 64;
    const float* sRow = s + (size_t)bh * NNODES;
    const float* dRow = d + (size_t)bh * NNODES;
    const float* xpB = xp + (size_t)b * NNODES * FG + h * OF;

    if (tid < 64) {
        int i = dst0 + tid;
        float dv = dRow[i];
        dS[tid] = dv;
        mS[tid] = lrelu(fmaxf(decf(smaxu[bh * 2 + 1]), sRow[i]) + dv);
    }
    int txf = lt & 7, tyd = lt >> 3;
    int ssrc = lt & 31, dgrp = lt >> 5;
    float acc[4][4] = {};
    float zacc[4] = {0.f, 0.f, 0.f, 0.f};

    #pragma unroll 1
    for (int c = 0; c < 4; c++) {
        int chunk = grp * 4 + c;
        __syncthreads();
        #pragma unroll
        for (int q = 0; q < 2; q++) {
            int v = lt + q * 128;
            int src = v >> 3, feat = (v & 7) << 2;
            *(float4*)&xS[grp][src * 32 + feat] =
                *(const float4*)&xpB[(size_t)(NSEC + chunk * 32 + src) * FG + feat];
        }
        if (lt < 32) sS[grp][lt] = sRow[NSEC + chunk * 32 + lt];
        __syncthreads();
        float sv = sS[grp][ssrc];
        #pragma unroll
        for (int r = 0; r < 16; r++) {
            int dd = dgrp * 16 + r;
            wS[grp][dd * 33 + ssrc] = __expf(lrelu(sv + dS[dd]) - mS[dd]);
        }
        __syncthreads();
        #pragma unroll 8
        for (int k = 0; k < 32; k++) {
            float4 x = *(const float4*)&xS[grp][k * 32 + 4 * txf];
            #pragma unroll
            for (int r = 0; r < 4; r++) {
                float w = wS[grp][(4 * tyd + r) * 33 + k];
                acc[r][0] = fmaf(w, x.x, acc[r][0]);
                acc[r][1] = fmaf(w, x.y, acc[r][1]);
                acc[r][2] = fmaf(w, x.z, acc[r][2]);
                acc[r][3] = fmaf(w, x.w, acc[r][3]);
                if (txf == 0) zacc[r] += w;
            }
        }
    }
    __syncthreads();
    if (txf == 0) {
        #pragma unroll
        for (int r = 0; r < 4; r++) zS[grp][4 * tyd + r] = zacc[r];
    }
    if (grp == 1) {
        #pragma unroll
        for (int r = 0; r < 4; r++) {
            float4 o = {acc[r][0], acc[r][1], acc[r][2], acc[r][3]};
            *(float4*)&comb[(4 * tyd + r) * 32 + 4 * txf] = o;
        }
    }
    __syncthreads();
    if (grp == 0) {
        float4 bv = *(const float4*)&bias[h * OF + 4 * txf];
        #pragma unroll
        for (int r = 0; r < 4; r++) {
            int li = 4 * tyd + r;
            int i = dst0 + li;
            float4 c4 = *(const float4*)&comb[li * 32 + 4 * txf];
            float ws = __expf(lrelu(sRow[i] + dS[li]) - mS[li]);
            float4 xs = *(const float4*)&xpB[(size_t)i * FG + 4 * txf];
            float inv = 1.f / (zS[0][li] + zS[1][li] + ws);
            float4 o;
            o.x = fmaxf((fmaf(ws, xs.x, acc[r][0] + c4.x)) * inv + bv.x, 0.f);
            o.y = fmaxf((fmaf(ws, xs.y, acc[r][1] + c4.y)) * inv + bv.y, 0.f);
            o.z = fmaxf((fmaf(ws, xs.z, acc[r][2] + c4.z)) * inv + bv.z, 0.f);
            o.w = fmaxf((fmaf(ws, xs.w, acc[r][3] + c4.w)) * inv + bv.w, 0.f);
            *(float4*)&out[(size_t)b * outStrideB + (size_t)i * FG + h * OF + 4 * txf] = o;
        }
    }
}

// ---------------- beam-destination aggregation, k-split partial pass -------
__global__ void beam_agg_part3_kernel(const float* __restrict__ xp, const float* __restrict__ s,
                                      const float* __restrict__ d, const unsigned* __restrict__ smaxu,
                                      float* __restrict__ pfeat, float* __restrict__ pZ)
{
    __shared__ float xS[2][32 * 32];
    __shared__ float wS[2][64 * 33];
    __shared__ float sS[2][32];
    __shared__ float dS[64], mS[64];
    __shared__ float comb[64 * 32];
    __shared__ float zS[2][64];
    int tid = threadIdx.x;
    int grp = tid >> 7, lt = tid & 127;
    int bh = blockIdx.z;
    int b = bh >> 2, h = bh & 3;
    int dst0 = blockIdx.x * 64;
    int kblk = blockIdx.y;
    const float* sRow = s + (size_t)bh * NNODES;
    const float* dRow = d + (size_t)bh * NNODES;
    const float* xpB = xp + (size_t)b * NNODES * FG + h * OF;

    if (tid < 64) {
        int j = dst0 + tid;
        float dv = dRow[NSEC + j];
        dS[tid] = dv;
        float sP = sRow[NSEC + NPRIM + j];
        float sB = sRow[NSEC + j];
        mS[tid] = lrelu(fmaxf(fmaxf(decf(smaxu[bh * 2]), sP), sB) + dv);
    }
    int txf = lt & 7, tyd = lt >> 3;
    int ssrc = lt & 31, dgrp = lt >> 5;
    float acc[4][4] = {};
    float zacc[4] = {0.f, 0.f, 0.f, 0.f};

    #pragma unroll 1
    for (int c = 0; c < 4; c++) {
        int chunk = grp * 4 + c;
        __syncthreads();
        #pragma unroll
        for (int q = 0; q < 2; q++) {
            int v = lt + q * 128;
            int src = v >> 3, feat = (v & 7) << 2;
            *(float4*)&xS[grp][src * 32 + feat] =
                *(const float4*)&xpB[(size_t)(kblk * 256 + chunk * 32 + src) * FG + feat];
        }
        if (lt < 32) sS[grp][lt] = sRow[kblk * 256 + chunk * 32 + lt];
        __syncthreads();
        float sv = sS[grp][ssrc];
        #pragma unroll
        for (int r = 0; r < 16; r++) {
            int dd = dgrp * 16 + r;
            wS[grp][dd * 33 + ssrc] = __expf(lrelu(sv + dS[dd]) - mS[dd]);
        }
        __syncthreads();
        #pragma unroll 8
        for (int k = 0; k < 32; k++) {
            float4 x = *(const float4*)&xS[grp][k * 32 + 4 * txf];
            #pragma unroll
            for (int r = 0; r < 4; r++) {
                float w = wS[grp][(4 * tyd + r) * 33 + k];
                acc[r][0] = fmaf(w, x.x, acc[r][0]);
                acc[r][1] = fmaf(w, x.y, acc[r][1]);
                acc[r][2] = fmaf(w, x.z, acc[r][2]);
                acc[r][3] = fmaf(w, x.w, acc[r][3]);
                if (txf == 0) zacc[r] += w;
            }
        }
    }
    __syncthreads();
    if (txf == 0) {
        #pragma unroll
        for (int r = 0; r < 4; r++) zS[grp][4 * tyd + r] = zacc[r];
    }
    if (grp == 1) {
        #pragma unroll
        for (int r = 0; r < 4; r++) {
            float4 o = {acc[r][0], acc[r][1], acc[r][2], acc[r][3]};
            *(float4*)&comb[(4 * tyd + r) * 32 + 4 * txf] = o;
        }
    }
    __syncthreads();
    if (grp == 0) {
        size_t pbase = (size_t)(bh * 4 + kblk) * 256;
        #pragma unroll
        for (int r = 0; r < 4; r++) {
            int li = 4 * tyd + r;
            int j = dst0 + li;
            float4 c4 = *(const float4*)&comb[li * 32 + 4 * txf];
            float4 o = {acc[r][0] + c4.x, acc[r][1] + c4.y,
                        acc[r][2] + c4.z, acc[r][3] + c4.w};
            *(float4*)&pfeat[(pbase + j) * 32 + 4 * txf] = o;
            if (txf == 0) pZ[pbase + j] = zS[0][li] + zS[1][li];
        }
    }
}

// ---------------- beam combine (fixed-order deterministic) -----------------
__global__ void beam_combine_kernel(const float* __restrict__ xp, const float* __restrict__ s,
                                    const float* __restrict__ d, const unsigned* __restrict__ smaxu,
                                    const float* __restrict__ pfeat, const float* __restrict__ pZ,
                                    const float* __restrict__ bias, float* __restrict__ out)
{
    int tid = threadIdx.x, warp = tid >> 5, lane = tid & 31;
    int bh = blockIdx.y, b = bh >> 2, h = bh & 3;
    int j = blockIdx.x * 8 + warp;
    const float* sRow = s + (size_t)bh * NNODES;
    const float* dRow = d + (size_t)bh * NNODES;
    float dv = dRow[NSEC + j];
    float sP = sRow[NSEC + NPRIM + j];
    float sB = sRow[NSEC + j];
    float m = lrelu(fmaxf(fmaxf(decf(smaxu[bh * 2]), sP), sB) + dv);
    float wp = __expf(lrelu(sP + dv) - m);
    float ws = __expf(lrelu(sB + dv) - m);
    size_t p0 = (size_t)bh * 4 * 256 + j;
    float Z = ((pZ[p0] + pZ[p0 + 256]) + pZ[p0 + 512]) + pZ[p0 + 768] + wp + ws;
    float acc = ((pfeat[p0 * 32 + lane] + pfeat[(p0 + 256) * 32 + lane])
                 + pfeat[(p0 + 512) * 32 + lane]) + pfeat[(p0 + 768) * 32 + lane];
    const float* xpB = xp + (size_t)b * NNODES * FG + h * OF;
    acc = fmaf(wp, xpB[(size_t)(NSEC + NPRIM + j) * FG + lane], acc);
    acc = fmaf(ws, xpB[(size_t)(NSEC + j) * FG + lane], acc);
    float v = acc / Z + bias[h * OF + lane];
    out[(size_t)b * NNODES * FG + (size_t)(NSEC + j) * FG + h * OF + lane] = fmaxf(v, 0.f);
}

// ---------------- ratio + smax reset ---------------------------------------
__global__ void ratio_kernel(const float* __restrict__ pP, const float* __restrict__ pT,
                             const float* __restrict__ part, float* __restrict__ ratio,
                             unsigned* __restrict__ smaxu)
{
    int tid = threadIdx.x;
    if (tid < 64) smaxu[tid] = 0u;       // reset both layers' encoded maxes for next replay
    int warp = tid >> 5, lane = tid & 31;
    if (warp >= BB) return;
    float ps = part[warp * 64 + lane] + part[warp * 64 + 32 + lane];
    ps = warpSum(ps);
    float pps = 0.f;
    #pragma unroll
    for (int k = 0; k < 8; k++) pps += pP[warp * 256 + lane + 32 * k];
    pps = warpSum(pps);
    if (lane == 0) {
        float num = fmaxf((*pT) - pps, 0.f);
        float r = num / (ps + 1e-5f);
        ratio[warp] = fminf(r, 1.f);
    }
}

__global__ void scale_kernel(float4* __restrict__ C, const float* __restrict__ ratio)
{
    int idx = blockIdx.x * 256 + threadIdx.x;     // 262144 float4s
    int b = idx >> 16;
    float r = ratio[b];
    float4 v = C[idx];
    v.x *= r; v.y *= r; v.z *= r; v.w *= r;
    v.x = (v.x > 0.001f) ? v.x : 0.f;
    v.y = (v.y > 0.001f) ? v.y : 0.f;
    v.z = (v.z > 0.001f) ? v.z : 0.f;
    v.w = (v.w > 0.001f) ? v.w : 0.f;
    C[idx] = v;
}

// ---------------- launch ----------------------------------------------------
extern "C" void kernel_launch(void* const* d_in, const int* in_sizes, int n_in,
                              void* d_out, int out_size)
{
    const float* h   = (const float*)d_in[0];
    const float* pP  = (const float*)d_in[1];
    const float* pT  = (const float*)d_in[2];
    const float* W0  = (const float*)d_in[3];
    const float* b0  = (const float*)d_in[4];
    const float* as0 = (const float*)d_in[5];
    const float* ad0 = (const float*)d_in[6];
    const float* W1  = (const float*)d_in[7];
    const float* b1  = (const float*)d_in[8];
    const float* as1 = (const float*)d_in[9];
    const float* ad1 = (const float*)d_in[10];
    const float* Wf0 = (const float*)d_in[11];
    const float* bf0 = (const float*)d_in[12];
    const float* Wf1 = (const float*)d_in[13];
    const float* bf1 = (const float*)d_in[14];
    float* out = (float*)d_out;

    float* base = nullptr;
    cudaGetSymbolAddress((void**)&base, g_scratch);
    float* xp1   = base;                 // 786432
    float* x1    = xp1 + 786432;         // 786432
    float* xp2   = x1 + 786432;          // 786432
    float* hg    = xp2 + 786432;         // 524288
    float* z     = hg + 524288;          // 1048576
    float* s1    = z + 1048576;          // 24576
    float* d1    = s1 + 24576;
    float* s2    = d1 + 24576;
    float* d2    = s2 + 24576;
    unsigned* smaxu = (unsigned*)(d2 + 24576);   // 64 (both layers)
    float* pfeat = d2 + 24576 + 64;      // 524288
    float* pZ    = pfeat + 524288;       // 16384
    float* part  = pZ + 16384;           // 256
    float* ratio = part + 256;           // 4
    unsigned* smax1u = smaxu;
    unsigned* smax2u = smaxu + 32;

    cudaStream_t sA;
    cudaStreamCreateWithFlags(&sA, cudaStreamNonBlocking);
    cudaEvent_t evFork, evJoin;
    cudaEventCreateWithFlags(&evFork, cudaEventDisableTiming);
    cudaEventCreateWithFlags(&evJoin, cudaEventDisableTiming);

    // Layer 1: GEMM with fused sd + segment-max (smaxu reset by prior replay's ratio_kernel;
    // zero-initialized device memory on the first call).
    gemm_kernel<<<dim3(2, 96), 256>>>(h, W0, nullptr, xp1, FG, FG, 24, 24, 0,
                                      nullptr, as0, ad0, s1, d1, smax1u);
    // fork: beam path on sA, sec path on default stream
    cudaEventRecord(evFork, 0);
    cudaStreamWaitEvent(sA, evFork, 0);
    beam_agg_part3_kernel<<<dim3(4, 4, 16), 256, 0, sA>>>(xp1, s1, d1, smax1u, pfeat, pZ);
    beam_combine_kernel<<<dim3(32, 16), 256, 0, sA>>>(xp1, s1, d1, smax1u, pfeat, pZ, b0, x1);
    sec_agg3_kernel<<<dim3(16, 16), 256>>>(xp1, s1, d1, smax1u, b0, x1, NNODES * FG);
    cudaEventRecord(evJoin, sA);
    cudaStreamWaitEvent(0, evJoin, 0);

    // Layer 2 (prim row-tiles skipped: 20 of 24 tiles per batch)
    gemm_kernel<<<dim3(2, 80), 256>>>(x1, W1, nullptr, xp2, FG, FG, 20, 24, 0,
                                      nullptr, as1, ad1, s2, d2, smax2u);
    sec_agg3_kernel<<<dim3(16, 16), 256>>>(xp2, s2, d2, smax2u, b1, hg, NSEC * FG);

    // FC stack
    gemm_kernel<<<dim3(4, 64), 256>>>(hg, Wf0, bf0, z, 256, FG, 64, 64, 1,
                                      nullptr, nullptr, nullptr, nullptr, nullptr, nullptr);
    gemm_kernel<<<dim3(4, 64), 256>>>(z, Wf1, bf1, out, 256, 256, 64, 64, 1,
                                      part, nullptr, nullptr, nullptr, nullptr, nullptr);

    // Power ratio (+ smax reset for next replay) + threshold
    ratio_kernel<<<1, 128>>>(pP, pT, part, ratio, smaxu);
    scale_kernel<<<1024, 256>>>((float4*)out, ratio);
}